// round 15
// baseline (speedup 1.0000x reference)
#include <cuda_runtime.h>
#include <cstddef>

// Problem constants
#define B_  8
#define T_  2048
#define D_  256
#define DK_ 64
#define NHEAD_ 4

// Fused attention kernel tiling
#define R_    16     // query rows per CTA
#define ST_   128    // key/value tile along s
#define TH_   512    // threads per CTA
#define KPAD  68
#define KBUF  8704   // 128*68 floats (one K buffer)
#define VBUF  8192   // 128*64 floats (one V buffer)
#define KVBUF 17408  // 2*KBUF = 2*VBUF+1024; also covers reduce buf 16*8*68=8704

// Scratch for projected q/k/v  (8*2048*64 fp32 = 4 MB each)
__device__ float g_qs[B_ * T_ * DK_];
__device__ float g_ks[B_ * T_ * DK_];
__device__ float g_vs[B_ * T_ * DK_];

// ---- packed f32x2 helpers (SASS FFMA2 — PTX-only pattern) ------------------
__device__ __forceinline__ void ffma2(unsigned long long& acc,
                                      unsigned long long a,
                                      unsigned long long b) {
    asm("fma.rn.f32x2 %0, %1, %2, %0;" : "+l"(acc) : "l"(a), "l"(b));
}
__device__ __forceinline__ unsigned long long pack2(float lo, float hi) {
    unsigned long long r;
    asm("mov.b64 %0, {%1, %2};" : "=l"(r) : "f"(lo), "f"(hi));
    return r;
}
__device__ __forceinline__ float pairsum(unsigned long long p) {
    float lo, hi;
    asm("mov.b64 {%0, %1}, %2;" : "=f"(lo), "=f"(hi) : "l"(p));
    return lo + hi;
}
__device__ __forceinline__ void unpack2(float& lo, float& hi, unsigned long long p) {
    asm("mov.b64 {%0, %1}, %2;" : "=f"(lo), "=f"(hi) : "l"(p));
}
__device__ __forceinline__ void stcs4(float* p, float4 v) {
    asm volatile("st.global.cs.v4.f32 [%0], {%1,%2,%3,%4};"
                 :: "l"(p), "f"(v.x), "f"(v.y), "f"(v.z), "f"(v.w) : "memory");
}

// ---------------------------------------------------------------------------
// Kernel 1: projections  qs = q@Wq, ks = k@Wk, vs = v@Wv
// grid = (256, 3), block = 256.  Each block: 64 rows x 64 cols (proven R5 shape)
// ---------------------------------------------------------------------------
#define PROJ_TH 256
#define PROJ_ROWS 64
#define PROJ_SMEM ((PROJ_ROWS * 256 + 256 * DK_) * 4)   // xs 64KB + Ws 64KB

__global__ __launch_bounds__(PROJ_TH, 1)
void proj_kernel(const float* __restrict__ q,
                 const float* __restrict__ k,
                 const float* __restrict__ v,
                 const float* __restrict__ Wq,
                 const float* __restrict__ Wk,
                 const float* __restrict__ Wv) {
    extern __shared__ float psm[];
    float* xs = psm;                       // 64*256
    float* Ws = psm + PROJ_ROWS * 256;     // 256*64

    const float* x;
    const float* W;
    float* dst;
    if (blockIdx.y == 0)      { x = q; W = Wq; dst = g_qs; }
    else if (blockIdx.y == 1) { x = k; W = Wk; dst = g_ks; }
    else                      { x = v; W = Wv; dst = g_vs; }

    const int row0 = blockIdx.x * PROJ_ROWS;
    const int tid  = threadIdx.x;

    {
        const float4* src4 = reinterpret_cast<const float4*>(x + (size_t)row0 * D_);
        float4* xs4 = reinterpret_cast<float4*>(xs);
        #pragma unroll
        for (int i = tid; i < PROJ_ROWS * 256 / 4; i += PROJ_TH) xs4[i] = src4[i];
        const float4* w4 = reinterpret_cast<const float4*>(W);
        float4* ws4 = reinterpret_cast<float4*>(Ws);
        #pragma unroll
        for (int i = tid; i < 256 * DK_ / 4; i += PROJ_TH) ws4[i] = w4[i];
    }
    __syncthreads();

    // thread tile: 4 rows x 4 cols
    const int jg = tid & 15;
    const int rg = tid >> 4;
    const int j0 = jg * 4;
    const int r0 = rg * 4;

    float acc[4][4];
    #pragma unroll
    for (int r = 0; r < 4; r++)
        #pragma unroll
        for (int c = 0; c < 4; c++) acc[r][c] = 0.f;

    for (int i = 0; i < D_; i += 4) {
        float4 xr[4];
        #pragma unroll
        for (int r = 0; r < 4; r++)
            xr[r] = *reinterpret_cast<const float4*>(&xs[(r0 + r) * 256 + i]);
        #pragma unroll
        for (int ii = 0; ii < 4; ii++) {
            float4 w = *reinterpret_cast<const float4*>(&Ws[(i + ii) * DK_ + j0]);
            #pragma unroll
            for (int r = 0; r < 4; r++) {
                const float xv = (ii == 0) ? xr[r].x : (ii == 1) ? xr[r].y
                                : (ii == 2) ? xr[r].z : xr[r].w;
                acc[r][0] += xv * w.x; acc[r][1] += xv * w.y;
                acc[r][2] += xv * w.z; acc[r][3] += xv * w.w;
            }
        }
    }

    #pragma unroll
    for (int r = 0; r < 4; r++) {
        float4* o = reinterpret_cast<float4*>(&dst[(size_t)(row0 + r0 + r) * DK_ + j0]);
        *o = make_float4(acc[r][0], acc[r][1], acc[r][2], acc[r][3]);
    }
}

// ---------------------------------------------------------------------------
// Kernel 2: fused  scores -> softmax -> (attn@V + attn stores) -> @Wo
// grid = 1024 CTAs, block = 512 threads.  Double-buffered smem tiles.
// smem: sc[16*2048] + kv[17408] + qh[1024] + rinv[16]  ~ 200 KB
// ---------------------------------------------------------------------------
#define SMEM_FLOATS (R_ * T_ + KVBUF + R_ * DK_ + 16)
#define SMEM_BYTES  (SMEM_FLOATS * 4)

__global__ __launch_bounds__(TH_, 1)
void attn_kernel(const float* __restrict__ Wo,
                 float* __restrict__ out,
                 float* __restrict__ attn_out) {
    extern __shared__ float sm[];
    float* sc   = sm;                        // 32768 floats (128 KB)
    float* kv   = sc + R_ * T_;              // 17408 floats (2 K bufs / 2 V bufs / reduce)
    float* qh   = kv + KVBUF;                // 1024 floats
    float* rinv = qh + R_ * DK_;             // 16

    const int tid  = threadIdx.x;
    const int lane = tid & 31;
    const int w    = tid >> 5;               // 16 warps
    const int b    = blockIdx.x >> 7;
    const int t0   = (blockIdx.x & 127) * R_;

    const float* ksrc = g_ks + (size_t)b * T_ * DK_;
    const float* vsrc = g_vs + (size_t)b * T_ * DK_;

    // ---- load q tile --------------------------------------------------------
    {
        const size_t qbase = ((size_t)b * T_ + t0) * DK_;
        for (int i = tid; i < R_ * DK_; i += TH_) qh[i] = g_qs[qbase + i];
    }

    // ---- phase 1: scores = qs . ks^T * 0.125 --------------------------------
    // warp = (rg: 4 row-groups of 4) x (sb: 4 s-blocks of 32)
    // lane = (sgl: 8 s) x (dq: 4 d-quarters of 16d); q REGISTER-RESIDENT.
    // Double-buffered K tiles, one sync per tile.
    {
        const int sgl = lane & 7, dq = lane >> 3;
        const int rg = w & 3, sb = w >> 2;
        const int r0 = rg * 4, d0 = dq * 16;

        // prefill K tile 0 into buffer 0
        {
            const float4* k4 = reinterpret_cast<const float4*>(ksrc);
            #pragma unroll
            for (int j = 0; j < 4; j++) {
                const int i = tid + TH_ * j;
                const int s = i >> 4, dc = i & 15;
                *reinterpret_cast<float4*>(&kv[s * KPAD + dc * 4]) = k4[i];
            }
        }
        __syncthreads();   // qh + tile 0 visible

        // q into registers: 4 rows x 4 pair-chunks (this thread's 16 d)
        ulonglong2 q2[4][4];
        #pragma unroll
        for (int r = 0; r < 4; r++)
            #pragma unroll
            for (int c = 0; c < 4; c++)
                q2[r][c] = *reinterpret_cast<const ulonglong2*>(
                    &qh[(r0 + r) * DK_ + d0 + c * 4]);

        for (int t = 0; t < T_ / ST_; t++) {
            const int st = t * ST_;
            const float* cur = kv + (t & 1) * KBUF;

            // prefetch next tile into registers
            float4 pf[4];
            if (t + 1 < T_ / ST_) {
                const float4* k4 =
                    reinterpret_cast<const float4*>(ksrc + (size_t)(st + ST_) * DK_);
                #pragma unroll
                for (int j = 0; j < 4; j++) pf[j] = k4[tid + TH_ * j];
            }

            unsigned long long acc2[4][4];
            #pragma unroll
            for (int r = 0; r < 4; r++)
                #pragma unroll
                for (int si = 0; si < 4; si++) acc2[r][si] = 0ULL;

            #pragma unroll
            for (int si = 0; si < 4; si++) {
                const int s = sb * 32 + sgl + 8 * si;
                #pragma unroll
                for (int c = 0; c < 4; c++) {
                    ulonglong2 k2 = *reinterpret_cast<const ulonglong2*>(
                        &cur[s * KPAD + d0 + c * 4]);
                    #pragma unroll
                    for (int r = 0; r < 4; r++) {
                        ffma2(acc2[r][si], q2[r][c].x, k2.x);
                        ffma2(acc2[r][si], q2[r][c].y, k2.y);
                    }
                }
            }

            // reduce over 4 d-quarters (shfl xor 8, 16); quarter dq writes row r==dq
            #pragma unroll
            for (int r = 0; r < 4; r++) {
                #pragma unroll
                for (int si = 0; si < 4; si++) {
                    float v = pairsum(acc2[r][si]);
                    v += __shfl_xor_sync(0xffffffffu, v, 8);
                    v += __shfl_xor_sync(0xffffffffu, v, 16);
                    if (r == dq)
                        sc[(r0 + r) * T_ + st + sb * 32 + sgl + 8 * si] = v * 0.125f;
                }
            }

            // store prefetched tile into the OTHER buffer
            if (t + 1 < T_ / ST_) {
                float* nxt = kv + ((t + 1) & 1) * KBUF;
                #pragma unroll
                for (int j = 0; j < 4; j++) {
                    const int i = tid + TH_ * j;
                    const int s = i >> 4, dc = i & 15;
                    *reinterpret_cast<float4*>(&nxt[s * KPAD + dc * 4]) = pf[j];
                }
            }
            __syncthreads();   // single barrier per tile
        }
    }

    // ---- V tile 0 prefetch (LDG now, STS after softmax -> overlapped) -------
    float4 v0pf[4];
    {
        const float4* v4 = reinterpret_cast<const float4*>(vsrc);
        #pragma unroll
        for (int j = 0; j < 4; j++) v0pf[j] = v4[tid + TH_ * j];
    }

    // ---- phase 2: softmax (one warp per row); sc keeps UNNORMALIZED exp -----
    {
        float* row = sc + w * T_;

        float m = -1e30f;
        for (int s = lane; s < T_; s += 32) m = fmaxf(m, row[s]);
        #pragma unroll
        for (int o = 16; o > 0; o >>= 1)
            m = fmaxf(m, __shfl_xor_sync(0xffffffffu, m, o));

        float sum = 0.f;
        for (int s = lane; s < T_; s += 32) {
            const float p = __expf(row[s] - m);
            row[s] = p;
            sum += p;
        }
        #pragma unroll
        for (int o = 16; o > 0; o >>= 1)
            sum += __shfl_xor_sync(0xffffffffu, sum, o);

        if (lane == 0) rinv[w] = 1.0f / sum;
    }

    // store V tile 0 into buffer 0 (kv free since phase-1 end)
    {
        float4* dst4 = reinterpret_cast<float4*>(kv);
        #pragma unroll
        for (int j = 0; j < 4; j++) dst4[tid + TH_ * j] = v0pf[j];
    }
    __syncthreads();   // rinv + V0 visible

    // ---- phase 4: head = p @ vs (unnormalized) + interleaved attn stores ----
    // warp = (rg: 2 row-groups of 8) x (schunk: 8 s-chunks of 16)
    // lane = (dgrp: 8) x (ssub: 4 of 4 consecutive s)
    // thread d-set: [dgrp*4, +4) U [32+dgrp*4, +4)  (conflict-free LDS.128)
    {
        const int dgrp = lane & 7, ssub = lane >> 3;
        const int rg = w & 1, schunk = w >> 1;
        const int s0 = schunk * 16 + ssub * 4;
        const int dA = dgrp * 4, dB = 32 + dgrp * 4;
        const size_t HTT   = (size_t)B_ * T_ * T_;
        const size_t abase = ((size_t)b * T_ + t0) * T_;

        unsigned long long acc2[8][4];
        #pragma unroll
        for (int r = 0; r < 8; r++)
            #pragma unroll
            for (int c = 0; c < 4; c++) acc2[r][c] = 0ULL;

        for (int t = 0; t < T_ / ST_; t++) {
            const int st = t * ST_;
            const float* cur = kv + (t & 1) * VBUF;

            float4 pf[4];
            if (t + 1 < T_ / ST_) {
                const float4* v4 =
                    reinterpret_cast<const float4*>(vsrc + (size_t)(st + ST_) * DK_);
                #pragma unroll
                for (int j = 0; j < 4; j++) pf[j] = v4[tid + TH_ * j];
            }

            // p for this thread's 4 s, 8 rows (one float4 per row)
            float4 p4[8];
            #pragma unroll
            for (int r = 0; r < 8; r++)
                p4[r] = *reinterpret_cast<const float4*>(
                    &sc[(rg * 8 + r) * T_ + st + s0]);

            #pragma unroll
            for (int j = 0; j < 4; j++) {
                const int sl = s0 + j;
                ulonglong2 vA = *reinterpret_cast<const ulonglong2*>(&cur[sl * DK_ + dA]);
                ulonglong2 vB = *reinterpret_cast<const ulonglong2*>(&cur[sl * DK_ + dB]);
                #pragma unroll
                for (int r = 0; r < 8; r++) {
                    const float pv = (j == 0) ? p4[r].x : (j == 1) ? p4[r].y
                                    : (j == 2) ? p4[r].z : p4[r].w;
                    const unsigned long long pp = pack2(pv, pv);
                    ffma2(acc2[r][0], pp, vA.x);
                    ffma2(acc2[r][1], pp, vA.y);
                    ffma2(acc2[r][2], pp, vB.x);
                    ffma2(acc2[r][3], pp, vB.y);
                }
            }

            // interleaved attn stores for this s-tile (normalized, 4 heads)
            {
                const int rr = tid >> 5;               // 16 rows
                const int s4 = tid & 31;               // 32 float4 groups
                float4 vv = *reinterpret_cast<const float4*>(
                    &sc[rr * T_ + st + s4 * 4]);
                const float inv = rinv[rr];
                vv.x *= inv; vv.y *= inv; vv.z *= inv; vv.w *= inv;
                const size_t off = abase + (size_t)rr * T_ + st + (size_t)s4 * 4;
                #pragma unroll
                for (int h = 0; h < NHEAD_; h++)
                    stcs4(attn_out + (size_t)h * HTT + off, vv);
            }

            // store prefetched V tile into the OTHER buffer
            if (t + 1 < T_ / ST_) {
                float4* dst4 = reinterpret_cast<float4*>(kv + ((t + 1) & 1) * VBUF);
                #pragma unroll
                for (int j = 0; j < 4; j++) dst4[tid + TH_ * j] = pf[j];
            }
            __syncthreads();   // single barrier per tile
        }

        // in-warp reduce over ssub (lane bits 3,4): shfl xor 8, 16 — once only
        float f[8][8];
        #pragma unroll
        for (int r = 0; r < 8; r++) {
            unpack2(f[r][0], f[r][1], acc2[r][0]);
            unpack2(f[r][2], f[r][3], acc2[r][1]);
            unpack2(f[r][4], f[r][5], acc2[r][2]);
            unpack2(f[r][6], f[r][7], acc2[r][3]);
            #pragma unroll
            for (int c = 0; c < 8; c++) {
                f[r][c] += __shfl_xor_sync(0xffffffffu, f[r][c], 8);
                f[r][c] += __shfl_xor_sync(0xffffffffu, f[r][c], 16);
            }
        }
        __syncthreads();   // all V reads done; reuse kv as reduce buffer

        // ssub==0 lanes store: buf[(schunk*2+rg)*8+dgrp] slot of 68 floats
        if (ssub == 0) {
            const int base = ((schunk * 2 + rg) * 8 + dgrp) * 68;
            #pragma unroll
            for (int r = 0; r < 8; r++) {
                *reinterpret_cast<float4*>(&kv[base + r * 8]) =
                    make_float4(f[r][0], f[r][1], f[r][2], f[r][3]);
                *reinterpret_cast<float4*>(&kv[base + r * 8 + 4]) =
                    make_float4(f[r][4], f[r][5], f[r][6], f[r][7]);
            }
        }
        __syncthreads();

        // gather over the 8 s-chunks; 1024 outputs (16r x 64d)
        #pragma unroll
        for (int it = 0; it < 2; it++) {
            const int item = tid + TH_ * it;
            const int row = item >> 6;
            const int d   = item & 63;
            const int rgp = row >> 3, r = row & 7;
            const int dg2 = (d & 31) >> 2;
            const int cpos = (d >> 5) * 4 + (d & 3);
            float s = 0.f;
            #pragma unroll
            for (int ch = 0; ch < 8; ch++)
                s += kv[((ch * 2 + rgp) * 8 + dg2) * 68 + r * 8 + cpos];
            qh[row * DK_ + d] = s * rinv[row];
        }
    }
    __syncthreads();

    // ---- phase 5: outputs = head @ Wo  (thread = column, 8 rows) ------------
    {
        const int c  = tid & 255;
        const int rh = tid >> 8;            // 2 row halves of 8
        float o[8];
        #pragma unroll
        for (int rr = 0; rr < 8; rr++) o[rr] = 0.f;

        for (int d = 0; d < DK_; d++) {
            const float wv = Wo[(size_t)d * D_ + c];
            #pragma unroll
            for (int rr = 0; rr < 8; rr++)
                o[rr] += qh[(rh * 8 + rr) * DK_ + d] * wv;
        }
        const size_t obase = ((size_t)b * T_ + t0 + rh * 8) * D_ + c;
        #pragma unroll
        for (int rr = 0; rr < 8; rr++) out[obase + (size_t)rr * D_] = o[rr];
    }
}

// ---------------------------------------------------------------------------
// launch
// ---------------------------------------------------------------------------
extern "C" void kernel_launch(void* const* d_in, const int* in_sizes, int n_in,
                              void* d_out, int out_size) {
    const float* q  = (const float*)d_in[0];
    const float* k  = (const float*)d_in[1];
    const float* v  = (const float*)d_in[2];
    const float* Wq = (const float*)d_in[3];
    const float* Wk = (const float*)d_in[4];
    const float* Wv = (const float*)d_in[5];
    const float* Wo = (const float*)d_in[6];

    float* out      = (float*)d_out;                               // [8,2048,256]
    float* attn_out = (float*)d_out + (size_t)B_ * T_ * D_;        // [4,8,2048,2048]

    cudaFuncSetAttribute(proj_kernel, cudaFuncAttributeMaxDynamicSharedMemorySize,
                         PROJ_SMEM);
    dim3 gp(16384 / PROJ_ROWS, 3, 1);
    proj_kernel<<<gp, PROJ_TH, PROJ_SMEM>>>(q, k, v, Wq, Wk, Wv);

    cudaFuncSetAttribute(attn_kernel, cudaFuncAttributeMaxDynamicSharedMemorySize,
                         SMEM_BYTES);
    attn_kernel<<<B_ * (T_ / R_), TH_, SMEM_BYTES>>>(Wo, out, attn_out);
}

// round 16
// speedup vs baseline: 1.1845x; 1.1845x over previous
#include <cuda_runtime.h>
#include <cstddef>

// Problem constants
#define B_  8
#define T_  2048
#define D_  256
#define DK_ 64
#define NHEAD_ 4

// Fused attention kernel tiling
#define R_    16     // query rows per CTA
#define ST_   128    // key/value tile along s
#define TH_   512    // threads per CTA
#define KPAD  68
#define KBUF  8704   // 128*68 floats (one K buffer)
#define VBUF  8192   // 128*64 floats (one V buffer)
#define KVBUF 17408  // 2*KBUF = 2*VBUF+1024; also covers reduce buf 512*33+31

// Scratch for projected q/k/v  (8*2048*64 fp32 = 4 MB each)
__device__ float g_qs[B_ * T_ * DK_];
__device__ float g_ks[B_ * T_ * DK_];
__device__ float g_vs[B_ * T_ * DK_];

// ---- packed f32x2 helpers (SASS FFMA2 — PTX-only pattern) ------------------
__device__ __forceinline__ void ffma2(unsigned long long& acc,
                                      unsigned long long a,
                                      unsigned long long b) {
    asm("fma.rn.f32x2 %0, %1, %2, %0;" : "+l"(acc) : "l"(a), "l"(b));
}
__device__ __forceinline__ unsigned long long pack2(float lo, float hi) {
    unsigned long long r;
    asm("mov.b64 %0, {%1, %2};" : "=l"(r) : "f"(lo), "f"(hi));
    return r;
}
__device__ __forceinline__ float pairsum(unsigned long long p) {
    float lo, hi;
    asm("mov.b64 {%0, %1}, %2;" : "=f"(lo), "=f"(hi) : "l"(p));
    return lo + hi;
}
__device__ __forceinline__ void unpack2(float& lo, float& hi, unsigned long long p) {
    asm("mov.b64 {%0, %1}, %2;" : "=f"(lo), "=f"(hi) : "l"(p));
}
__device__ __forceinline__ void stcs4(float* p, float4 v) {
    asm volatile("st.global.cs.v4.f32 [%0], {%1,%2,%3,%4};"
                 :: "l"(p), "f"(v.x), "f"(v.y), "f"(v.z), "f"(v.w) : "memory");
}

// ---------------------------------------------------------------------------
// Kernel 1: projections  qs = q@Wq, ks = k@Wk, vs = v@Wv
// grid = (256, 3), block = 256.  Each block: 64 rows x 64 cols (proven R15)
// ---------------------------------------------------------------------------
#define PROJ_TH 256
#define PROJ_ROWS 64
#define PROJ_SMEM ((PROJ_ROWS * 256 + 256 * DK_) * 4)   // xs 64KB + Ws 64KB

__global__ __launch_bounds__(PROJ_TH, 1)
void proj_kernel(const float* __restrict__ q,
                 const float* __restrict__ k,
                 const float* __restrict__ v,
                 const float* __restrict__ Wq,
                 const float* __restrict__ Wk,
                 const float* __restrict__ Wv) {
    extern __shared__ float psm[];
    float* xs = psm;                       // 64*256
    float* Ws = psm + PROJ_ROWS * 256;     // 256*64

    const float* x;
    const float* W;
    float* dst;
    if (blockIdx.y == 0)      { x = q; W = Wq; dst = g_qs; }
    else if (blockIdx.y == 1) { x = k; W = Wk; dst = g_ks; }
    else                      { x = v; W = Wv; dst = g_vs; }

    const int row0 = blockIdx.x * PROJ_ROWS;
    const int tid  = threadIdx.x;

    {
        const float4* src4 = reinterpret_cast<const float4*>(x + (size_t)row0 * D_);
        float4* xs4 = reinterpret_cast<float4*>(xs);
        #pragma unroll
        for (int i = tid; i < PROJ_ROWS * 256 / 4; i += PROJ_TH) xs4[i] = src4[i];
        const float4* w4 = reinterpret_cast<const float4*>(W);
        float4* ws4 = reinterpret_cast<float4*>(Ws);
        #pragma unroll
        for (int i = tid; i < 256 * DK_ / 4; i += PROJ_TH) ws4[i] = w4[i];
    }
    __syncthreads();

    // thread tile: 4 rows x 4 cols
    const int jg = tid & 15;
    const int rg = tid >> 4;
    const int j0 = jg * 4;
    const int r0 = rg * 4;

    float acc[4][4];
    #pragma unroll
    for (int r = 0; r < 4; r++)
        #pragma unroll
        for (int c = 0; c < 4; c++) acc[r][c] = 0.f;

    for (int i = 0; i < D_; i += 4) {
        float4 xr[4];
        #pragma unroll
        for (int r = 0; r < 4; r++)
            xr[r] = *reinterpret_cast<const float4*>(&xs[(r0 + r) * 256 + i]);
        #pragma unroll
        for (int ii = 0; ii < 4; ii++) {
            float4 w = *reinterpret_cast<const float4*>(&Ws[(i + ii) * DK_ + j0]);
            #pragma unroll
            for (int r = 0; r < 4; r++) {
                const float xv = (ii == 0) ? xr[r].x : (ii == 1) ? xr[r].y
                                : (ii == 2) ? xr[r].z : xr[r].w;
                acc[r][0] += xv * w.x; acc[r][1] += xv * w.y;
                acc[r][2] += xv * w.z; acc[r][3] += xv * w.w;
            }
        }
    }

    #pragma unroll
    for (int r = 0; r < 4; r++) {
        float4* o = reinterpret_cast<float4*>(&dst[(size_t)(row0 + r0 + r) * DK_ + j0]);
        *o = make_float4(acc[r][0], acc[r][1], acc[r][2], acc[r][3]);
    }
}

// ---------------------------------------------------------------------------
// Kernel 2: fused  scores -> softmax -> (attn@V + attn stores) -> @Wo
// EXACT R14 kernel (measured 359.7 us).  Double-buffered smem tiles,
// ONE barrier per tile.  smem: sc[16*2048] + kv[17408] + qh[1024] + rinv[16]
// ---------------------------------------------------------------------------
#define SMEM_FLOATS (R_ * T_ + KVBUF + R_ * DK_ + 16)
#define SMEM_BYTES  (SMEM_FLOATS * 4)

__global__ __launch_bounds__(TH_, 1)
void attn_kernel(const float* __restrict__ Wo,
                 float* __restrict__ out,
                 float* __restrict__ attn_out) {
    extern __shared__ float sm[];
    float* sc   = sm;                        // 32768 floats (128 KB)
    float* kv   = sc + R_ * T_;              // 17408 floats (2 K bufs / 2 V bufs / reduce)
    float* qh   = kv + KVBUF;                // 1024 floats
    float* rinv = qh + R_ * DK_;             // 16

    const int tid  = threadIdx.x;
    const int lane = tid & 31;
    const int w    = tid >> 5;               // 16 warps
    const int b    = blockIdx.x >> 7;
    const int t0   = (blockIdx.x & 127) * R_;

    const float* ksrc = g_ks + (size_t)b * T_ * DK_;
    const float* vsrc = g_vs + (size_t)b * T_ * DK_;

    // ---- load q tile --------------------------------------------------------
    {
        const size_t qbase = ((size_t)b * T_ + t0) * DK_;
        for (int i = tid; i < R_ * DK_; i += TH_) qh[i] = g_qs[qbase + i];
    }

    // ---- phase 1: scores = qs . ks^T * 0.125 --------------------------------
    // warp = (rg: 4 row-groups of 4) x (sb: 4 s-blocks of 32)
    // lane = (sgl: 8 s) x (dq: 4 d-quarters of 16d); q REGISTER-RESIDENT.
    // Double-buffered K tiles, one sync per tile.
    {
        const int sgl = lane & 7, dq = lane >> 3;
        const int rg = w & 3, sb = w >> 2;
        const int r0 = rg * 4, d0 = dq * 16;

        // prefill K tile 0 into buffer 0
        {
            const float4* k4 = reinterpret_cast<const float4*>(ksrc);
            #pragma unroll
            for (int j = 0; j < 4; j++) {
                const int i = tid + TH_ * j;
                const int s = i >> 4, dc = i & 15;
                *reinterpret_cast<float4*>(&kv[s * KPAD + dc * 4]) = k4[i];
            }
        }
        __syncthreads();   // qh + tile 0 visible

        // q into registers: 4 rows x 4 pair-chunks (this thread's 16 d)
        ulonglong2 q2[4][4];
        #pragma unroll
        for (int r = 0; r < 4; r++)
            #pragma unroll
            for (int c = 0; c < 4; c++)
                q2[r][c] = *reinterpret_cast<const ulonglong2*>(
                    &qh[(r0 + r) * DK_ + d0 + c * 4]);

        for (int t = 0; t < T_ / ST_; t++) {
            const int st = t * ST_;
            const float* cur = kv + (t & 1) * KBUF;

            // prefetch next tile into registers
            float4 pf[4];
            if (t + 1 < T_ / ST_) {
                const float4* k4 =
                    reinterpret_cast<const float4*>(ksrc + (size_t)(st + ST_) * DK_);
                #pragma unroll
                for (int j = 0; j < 4; j++) pf[j] = k4[tid + TH_ * j];
            }

            unsigned long long acc2[4][4];
            #pragma unroll
            for (int r = 0; r < 4; r++)
                #pragma unroll
                for (int si = 0; si < 4; si++) acc2[r][si] = 0ULL;

            #pragma unroll
            for (int si = 0; si < 4; si++) {
                const int s = sb * 32 + sgl + 8 * si;
                #pragma unroll
                for (int c = 0; c < 4; c++) {
                    ulonglong2 k2 = *reinterpret_cast<const ulonglong2*>(
                        &cur[s * KPAD + d0 + c * 4]);
                    #pragma unroll
                    for (int r = 0; r < 4; r++) {
                        ffma2(acc2[r][si], q2[r][c].x, k2.x);
                        ffma2(acc2[r][si], q2[r][c].y, k2.y);
                    }
                }
            }

            // reduce over 4 d-quarters (shfl xor 8, 16); quarter dq writes row r==dq
            #pragma unroll
            for (int r = 0; r < 4; r++) {
                #pragma unroll
                for (int si = 0; si < 4; si++) {
                    float v = pairsum(acc2[r][si]);
                    v += __shfl_xor_sync(0xffffffffu, v, 8);
                    v += __shfl_xor_sync(0xffffffffu, v, 16);
                    if (r == dq)
                        sc[(r0 + r) * T_ + st + sb * 32 + sgl + 8 * si] = v * 0.125f;
                }
            }

            // store prefetched tile into the OTHER buffer
            if (t + 1 < T_ / ST_) {
                float* nxt = kv + ((t + 1) & 1) * KBUF;
                #pragma unroll
                for (int j = 0; j < 4; j++) {
                    const int i = tid + TH_ * j;
                    const int s = i >> 4, dc = i & 15;
                    *reinterpret_cast<float4*>(&nxt[s * KPAD + dc * 4]) = pf[j];
                }
            }
            __syncthreads();   // single barrier per tile
        }
    }

    // ---- V tile 0 prefetch (LDG now, STS after softmax -> overlapped) -------
    float4 v0pf[4];
    {
        const float4* v4 = reinterpret_cast<const float4*>(vsrc);
        #pragma unroll
        for (int j = 0; j < 4; j++) v0pf[j] = v4[tid + TH_ * j];
    }

    // ---- phase 2: softmax (one warp per row); sc keeps UNNORMALIZED exp -----
    {
        float* row = sc + w * T_;

        float m = -1e30f;
        for (int s = lane; s < T_; s += 32) m = fmaxf(m, row[s]);
        #pragma unroll
        for (int o = 16; o > 0; o >>= 1)
            m = fmaxf(m, __shfl_xor_sync(0xffffffffu, m, o));

        float sum = 0.f;
        for (int s = lane; s < T_; s += 32) {
            const float p = __expf(row[s] - m);
            row[s] = p;
            sum += p;
        }
        #pragma unroll
        for (int o = 16; o > 0; o >>= 1)
            sum += __shfl_xor_sync(0xffffffffu, sum, o);

        if (lane == 0) rinv[w] = 1.0f / sum;
    }

    // store V tile 0 into buffer 0 (kv free since phase-1 end)
    {
        float4* dst4 = reinterpret_cast<float4*>(kv);
        #pragma unroll
        for (int j = 0; j < 4; j++) dst4[tid + TH_ * j] = v0pf[j];
    }
    __syncthreads();   // rinv + V0 visible

    // ---- phase 4: head = p @ vs (unnormalized) + interleaved attn stores ----
    // thread tile 8r x 4d, s split 16 ways (8 s per thread per 128-tile).
    // Double-buffered V tiles, one sync per tile.
    {
        const int rg4 = lane >> 4;          // 0..1 (8 rows each)
        const int dg  = lane & 15;          // 16 d groups
        const int ss  = w;                  // 16 s subgroups
        const int d4  = dg * 4;
        const size_t HTT   = (size_t)B_ * T_ * T_;
        const size_t abase = ((size_t)b * T_ + t0) * T_;

        unsigned long long acc2[8][2];
        #pragma unroll
        for (int r = 0; r < 8; r++) { acc2[r][0] = 0ULL; acc2[r][1] = 0ULL; }

        for (int t = 0; t < T_ / ST_; t++) {
            const int st = t * ST_;
            const float* cur = kv + (t & 1) * VBUF;

            float4 pf[4];
            if (t + 1 < T_ / ST_) {
                const float4* v4 =
                    reinterpret_cast<const float4*>(vsrc + (size_t)(st + ST_) * DK_);
                #pragma unroll
                for (int j = 0; j < 4; j++) pf[j] = v4[tid + TH_ * j];
            }

            const int sb = ss * 8;
            #pragma unroll
            for (int j4 = 0; j4 < 2; j4++) {
                const int s0 = sb + j4 * 4;
                float4 p4[8];
                #pragma unroll
                for (int r = 0; r < 8; r++)
                    p4[r] = *reinterpret_cast<const float4*>(
                        &sc[(rg4 * 8 + r) * T_ + st + s0]);
                ulonglong2 v2[4];
                #pragma unroll
                for (int js = 0; js < 4; js++)
                    v2[js] = *reinterpret_cast<const ulonglong2*>(
                        &cur[(s0 + js) * DK_ + d4]);
                #pragma unroll
                for (int js = 0; js < 4; js++)
                    #pragma unroll
                    for (int r = 0; r < 8; r++) {
                        const float pv = (js == 0) ? p4[r].x : (js == 1) ? p4[r].y
                                        : (js == 2) ? p4[r].z : p4[r].w;
                        const unsigned long long pp = pack2(pv, pv);
                        ffma2(acc2[r][0], pp, v2[js].x);
                        ffma2(acc2[r][1], pp, v2[js].y);
                    }
            }

            // interleaved attn stores for this s-tile (normalized, 4 heads)
            {
                const int rr = tid >> 5;               // 16 rows
                const int s4 = tid & 31;               // 32 float4 groups
                float4 vv = *reinterpret_cast<const float4*>(
                    &sc[rr * T_ + st + s4 * 4]);
                const float inv = rinv[rr];
                vv.x *= inv; vv.y *= inv; vv.z *= inv; vv.w *= inv;
                const size_t off = abase + (size_t)rr * T_ + st + (size_t)s4 * 4;
                #pragma unroll
                for (int h = 0; h < NHEAD_; h++)
                    stcs4(attn_out + (size_t)h * HTT + off, vv);
            }

            // store prefetched V tile into the OTHER buffer
            if (t + 1 < T_ / ST_) {
                float4* dst4 = reinterpret_cast<float4*>(kv + ((t + 1) & 1) * VBUF);
                #pragma unroll
                for (int j = 0; j < 4; j++) dst4[tid + TH_ * j] = pf[j];
            }
            __syncthreads();   // single barrier per tile
        }

        // write partials (stride 33: bank-conflict-free) and reduce 16 ss groups
        #pragma unroll
        for (int r = 0; r < 8; r++) {
            float a0, a1, a2, a3;
            unpack2(a0, a1, acc2[r][0]);
            unpack2(a2, a3, acc2[r][1]);
            kv[tid * 33 + r * 4 + 0] = a0;
            kv[tid * 33 + r * 4 + 1] = a1;
            kv[tid * 33 + r * 4 + 2] = a2;
            kv[tid * 33 + r * 4 + 3] = a3;
        }
        __syncthreads();

        #pragma unroll
        for (int it = 0; it < 2; it++) {
            const int item = tid + TH_ * it;           // 1024 = 16r x 64d
            const int orr = item >> 6;
            const int od  = item & 63;
            const int rgp = orr >> 3;
            const int dgp = od >> 2;
            const int jloc = (orr & 7) * 4 + (od & 3);
            float s = 0.f;
            #pragma unroll
            for (int j = 0; j < 16; j++)
                s += kv[(j * 32 + rgp * 16 + dgp) * 33 + jloc];
            qh[orr * DK_ + od] = s * rinv[orr];
        }
    }
    __syncthreads();

    // ---- phase 5: outputs = head @ Wo  (thread = column, 8 rows) ------------
    {
        const int c  = tid & 255;
        const int rh = tid >> 8;            // 2 row halves of 8
        float o[8];
        #pragma unroll
        for (int rr = 0; rr < 8; rr++) o[rr] = 0.f;

        for (int d = 0; d < DK_; d++) {
            const float wv = Wo[(size_t)d * D_ + c];
            #pragma unroll
            for (int rr = 0; rr < 8; rr++)
                o[rr] += qh[(rh * 8 + rr) * DK_ + d] * wv;
        }
        const size_t obase = ((size_t)b * T_ + t0 + rh * 8) * D_ + c;
        #pragma unroll
        for (int rr = 0; rr < 8; rr++) out[obase + (size_t)rr * D_] = o[rr];
    }
}

// ---------------------------------------------------------------------------
// launch
// ---------------------------------------------------------------------------
extern "C" void kernel_launch(void* const* d_in, const int* in_sizes, int n_in,
                              void* d_out, int out_size) {
    const float* q  = (const float*)d_in[0];
    const float* k  = (const float*)d_in[1];
    const float* v  = (const float*)d_in[2];
    const float* Wq = (const float*)d_in[3];
    const float* Wk = (const float*)d_in[4];
    const float* Wv = (const float*)d_in[5];
    const float* Wo = (const float*)d_in[6];

    float* out      = (float*)d_out;                               // [8,2048,256]
    float* attn_out = (float*)d_out + (size_t)B_ * T_ * D_;        // [4,8,2048,2048]

    cudaFuncSetAttribute(proj_kernel, cudaFuncAttributeMaxDynamicSharedMemorySize,
                         PROJ_SMEM);
    dim3 gp(16384 / PROJ_ROWS, 3, 1);
    proj_kernel<<<gp, PROJ_TH, PROJ_SMEM>>>(q, k, v, Wq, Wk, Wv);

    cudaFuncSetAttribute(attn_kernel, cudaFuncAttributeMaxDynamicSharedMemorySize,
                         SMEM_BYTES);
    attn_kernel<<<B_ * (T_ / R_), TH_, SMEM_BYTES>>>(Wo, out, attn_out);
}